// round 1
// baseline (speedup 1.0000x reference)
#include <cuda_runtime.h>

#define T_STEPS 512
#define HID 64

// packed fp32x2 FMA: d.lo += a.lo*b.lo ; d.hi += a.hi*b.hi  (Blackwell FFMA2, PTX-only)
__device__ __forceinline__ void fma2(unsigned long long &d, unsigned long long a, unsigned long long b) {
    asm("fma.rn.f32x2 %0, %1, %2, %0;" : "+l"(d) : "l"(a), "l"(b));
}
__device__ __forceinline__ unsigned long long add2(unsigned long long a, unsigned long long b) {
    unsigned long long r;
    asm("add.rn.f32x2 %0, %1, %2;" : "=l"(r) : "l"(a), "l"(b));
    return r;
}
__device__ __forceinline__ float hsum2(unsigned long long v) {
    float lo, hi;
    asm("mov.b64 {%0,%1}, %2;" : "=f"(lo), "=f"(hi) : "l"(v));
    return lo + hi;
}

// tanh(x) = 1 - 2/(e^{2x}+1).  __expf -> MUFU.EX2 path (2 ulp), __fdividef -> MUFU.RCP.
// Clamp keeps e^{2x} finite and __fdividef in its exact-result range.
// Absolute error ~1e-7, far under the 1e-3 rel-err budget even over 512 steps.
__device__ __forceinline__ float tanh_fast(float x) {
    float xc = fminf(fmaxf(x, -10.0f), 10.0f);
    float e  = __expf(xc + xc);
    return 1.0f - __fdividef(2.0f, e + 1.0f);
}

__global__ __launch_bounds__(32, 14)
void rnn_warp_kernel(const float* __restrict__ x,
                     const float* __restrict__ W_ih,
                     const float* __restrict__ W_hh,
                     const float* __restrict__ b_ih,
                     const float* __restrict__ b_hh,
                     const float* __restrict__ fc_w,
                     const float* __restrict__ fc_b,
                     float* __restrict__ out)
{
    __shared__ __align__(16) float sx[T_STEPS];
    __shared__ __align__(16) float hbuf[2][HID];

    const int lane = threadIdx.x;   // 32 threads: lane owns output rows (lane, lane+32)
    const int b    = blockIdx.x;

    // W_hh rows `lane` and `lane+32`, register-resident as f32x2 j-pairs (128 regs).
    // new_h[i] = tanh(xp[i] + sum_j h[j] * W_hh[i][j])  (row-major [i][j], 8B-aligned rows)
    unsigned long long w0[32], w1[32];
    const unsigned long long* wr0 = reinterpret_cast<const unsigned long long*>(W_hh + lane * HID);
    const unsigned long long* wr1 = reinterpret_cast<const unsigned long long*>(W_hh + (lane + 32) * HID);
#pragma unroll
    for (int p = 0; p < 32; ++p) { w0[p] = wr0[p]; w1[p] = wr1[p]; }

    const float wih0  = W_ih[lane];
    const float wih1  = W_ih[lane + 32];
    const float bias0 = b_ih[lane]      + b_hh[lane];
    const float bias1 = b_ih[lane + 32] + b_hh[lane + 32];

    // Stage this batch's x[t] sequence into shared (I=1 => contiguous 512 floats).
    const float4* xg  = reinterpret_cast<const float4*>(x + (size_t)b * T_STEPS);
    float4*       sx4 = reinterpret_cast<float4*>(sx);
#pragma unroll
    for (int i = 0; i < 4; ++i) sx4[lane + 32 * i] = xg[lane + 32 * i];

    hbuf[0][lane]      = 0.0f;
    hbuf[0][lane + 32] = 0.0f;
    __syncwarp();

    auto step = [&](int t, const float* hr, float* hw) {
        const ulonglong2* hp = reinterpret_cast<const ulonglong2*>(hr);
        // 4 independent FFMA2 chains (2 per output row) for ILP.
        unsigned long long a0a = 0ull, a0b = 0ull, a1a = 0ull, a1b = 0ull;
#pragma unroll
        for (int k = 0; k < 8; ++k) {              // h[0..31]
            ulonglong2 h2 = hp[k];                 // one LDS.128 broadcast -> 2 f32x2 pairs
            fma2(a0a, h2.x, w0[2 * k]);  fma2(a0a, h2.y, w0[2 * k + 1]);
            fma2(a1a, h2.x, w1[2 * k]);  fma2(a1a, h2.y, w1[2 * k + 1]);
        }
#pragma unroll
        for (int k = 8; k < 16; ++k) {             // h[32..63]
            ulonglong2 h2 = hp[k];
            fma2(a0b, h2.x, w0[2 * k]);  fma2(a0b, h2.y, w0[2 * k + 1]);
            fma2(a1b, h2.x, w1[2 * k]);  fma2(a1b, h2.y, w1[2 * k + 1]);
        }
        float xt = sx[t];
        float s0 = hsum2(add2(a0a, a0b)) + fmaf(xt, wih0, bias0);
        float s1 = hsum2(add2(a1a, a1b)) + fmaf(xt, wih1, bias1);
        hw[lane]      = tanh_fast(s0);
        hw[lane + 32] = tanh_fast(s1);
        __syncwarp();   // one sync/step; double-buffering makes it sufficient
    };

#pragma unroll 1
    for (int t = 0; t < T_STEPS; t += 2) {
        step(t,     hbuf[0], hbuf[1]);
        step(t + 1, hbuf[1], hbuf[0]);
    }

    // Final FC: out[b] = sum_h hT[h]*fc_w[h] + fc_b
    float hf0 = hbuf[0][lane];
    float hf1 = hbuf[0][lane + 32];
    float v = fmaf(hf0, fc_w[lane], hf1 * fc_w[lane + 32]);
#pragma unroll
    for (int o = 16; o; o >>= 1) v += __shfl_xor_sync(0xffffffffu, v, o);
    if (lane == 0) out[b] = v + fc_b[0];
}

extern "C" void kernel_launch(void* const* d_in, const int* in_sizes, int n_in,
                              void* d_out, int out_size)
{
    const float* x    = (const float*)d_in[0];  // [B, T, 1]
    const float* W_ih = (const float*)d_in[1];  // [64, 1]
    const float* W_hh = (const float*)d_in[2];  // [64, 64]
    const float* b_ih = (const float*)d_in[3];  // [64]
    const float* b_hh = (const float*)d_in[4];  // [64]
    const float* fc_w = (const float*)d_in[5];  // [1, 64]
    const float* fc_b = (const float*)d_in[6];  // [1]
    float* out = (float*)d_out;                 // [B, 1]

    int B = in_sizes[0] / T_STEPS;              // I == 1
    rnn_warp_kernel<<<B, 32>>>(x, W_ih, W_hh, b_ih, b_hh, fc_w, fc_b, out);
}

// round 2
// speedup vs baseline: 1.5792x; 1.5792x over previous
#include <cuda_runtime.h>

#define T_STEPS 512
#define HID 64

// packed fp32x2 FMA: d.lo += a.lo*b.lo ; d.hi += a.hi*b.hi  (Blackwell FFMA2, PTX-only)
__device__ __forceinline__ void fma2(unsigned long long &d, unsigned long long a, unsigned long long b) {
    asm("fma.rn.f32x2 %0, %1, %2, %0;" : "+l"(d) : "l"(a), "l"(b));
}
__device__ __forceinline__ unsigned long long add2(unsigned long long a, unsigned long long b) {
    unsigned long long r;
    asm("add.rn.f32x2 %0, %1, %2;" : "=l"(r) : "l"(a), "l"(b));
    return r;
}
__device__ __forceinline__ float hsum2(unsigned long long v) {
    float lo, hi;
    asm("mov.b64 {%0,%1}, %2;" : "=f"(lo), "=f"(hi) : "l"(v));
    return lo + hi;
}

// tanh(x) = 1 - 2/(e^{2x}+1).  __expf -> MUFU.EX2, __fdividef -> MUFU.RCP.
// abs err ~1e-7 << 1e-3 budget.
__device__ __forceinline__ float tanh_fast(float x) {
    float xc = fminf(fmaxf(x, -10.0f), 10.0f);
    float e  = __expf(xc + xc);
    return 1.0f - __fdividef(2.0f, e + 1.0f);
}

// NOTE: no __launch_bounds__ register cap. W_hh rows (128 regs) MUST stay in the RF;
// R1's cap at 146 regs spilled them to local (L1tex 77% busy, 418us). ~155 regs ->
// ~13 CTAs/SM, same residency as R1 but zero spill traffic.
__global__ void rnn_warp_kernel(const float* __restrict__ x,
                                const float* __restrict__ W_ih,
                                const float* __restrict__ W_hh,
                                const float* __restrict__ b_ih,
                                const float* __restrict__ b_hh,
                                const float* __restrict__ fc_w,
                                const float* __restrict__ fc_b,
                                float* __restrict__ out)
{
    __shared__ __align__(16) float sx[T_STEPS];
    __shared__ __align__(16) float hbuf[2][HID];

    const int lane = threadIdx.x;   // 32 threads: lane owns output rows (lane, lane+32)
    const int b    = blockIdx.x;

    // W_hh rows `lane` and `lane+32`, register-resident as f32x2 j-pairs (128 regs).
    unsigned long long w0[32], w1[32];
    const unsigned long long* wr0 = reinterpret_cast<const unsigned long long*>(W_hh + lane * HID);
    const unsigned long long* wr1 = reinterpret_cast<const unsigned long long*>(W_hh + (lane + 32) * HID);
#pragma unroll
    for (int p = 0; p < 32; ++p) { w0[p] = wr0[p]; w1[p] = wr1[p]; }

    const float wih0  = W_ih[lane];
    const float wih1  = W_ih[lane + 32];
    const float bias0 = b_ih[lane]      + b_hh[lane];
    const float bias1 = b_ih[lane + 32] + b_hh[lane + 32];

    // Stage this batch's x[t] sequence into shared (I=1 => contiguous 512 floats).
    const float4* xg  = reinterpret_cast<const float4*>(x + (size_t)b * T_STEPS);
    float4*       sx4 = reinterpret_cast<float4*>(sx);
#pragma unroll
    for (int i = 0; i < 4; ++i) sx4[lane + 32 * i] = xg[lane + 32 * i];

    hbuf[0][lane]      = 0.0f;
    hbuf[0][lane + 32] = 0.0f;
    __syncwarp();

    auto step = [&](int t, const float* hr, float* hw) {
        const ulonglong2* hp = reinterpret_cast<const ulonglong2*>(hr);
        // 4 independent FFMA2 chains (2 per output row) for ILP.
        unsigned long long a0a = 0ull, a0b = 0ull, a1a = 0ull, a1b = 0ull;
#pragma unroll
        for (int k = 0; k < 8; ++k) {              // h[0..31]
            ulonglong2 h2 = hp[k];                 // LDS.128 broadcast -> 2 f32x2 pairs
            fma2(a0a, h2.x, w0[2 * k]);  fma2(a0b, h2.y, w0[2 * k + 1]);
            fma2(a1a, h2.x, w1[2 * k]);  fma2(a1b, h2.y, w1[2 * k + 1]);
        }
#pragma unroll
        for (int k = 8; k < 16; ++k) {             // h[32..63]
            ulonglong2 h2 = hp[k];
            fma2(a0a, h2.x, w0[2 * k]);  fma2(a0b, h2.y, w0[2 * k + 1]);
            fma2(a1a, h2.x, w1[2 * k]);  fma2(a1b, h2.y, w1[2 * k + 1]);
        }
        float xt = sx[t];
        float s0 = hsum2(add2(a0a, a0b)) + fmaf(xt, wih0, bias0);
        float s1 = hsum2(add2(a1a, a1b)) + fmaf(xt, wih1, bias1);
        hw[lane]      = tanh_fast(s0);
        hw[lane + 32] = tanh_fast(s1);
        __syncwarp();   // one sync/step; double-buffering makes it sufficient
    };

#pragma unroll 1
    for (int t = 0; t < T_STEPS; t += 2) {
        step(t,     hbuf[0], hbuf[1]);
        step(t + 1, hbuf[1], hbuf[0]);
    }

    // Final FC: out[b] = sum_h hT[h]*fc_w[h] + fc_b
    float hf0 = hbuf[0][lane];
    float hf1 = hbuf[0][lane + 32];
    float v = fmaf(hf0, fc_w[lane], hf1 * fc_w[lane + 32]);
#pragma unroll
    for (int o = 16; o; o >>= 1) v += __shfl_xor_sync(0xffffffffu, v, o);
    if (lane == 0) out[b] = v + fc_b[0];
}

extern "C" void kernel_launch(void* const* d_in, const int* in_sizes, int n_in,
                              void* d_out, int out_size)
{
    const float* x    = (const float*)d_in[0];  // [B, T, 1]
    const float* W_ih = (const float*)d_in[1];  // [64, 1]
    const float* W_hh = (const float*)d_in[2];  // [64, 64]
    const float* b_ih = (const float*)d_in[3];  // [64]
    const float* b_hh = (const float*)d_in[4];  // [64]
    const float* fc_w = (const float*)d_in[5];  // [1, 64]
    const float* fc_b = (const float*)d_in[6];  // [1]
    float* out = (float*)d_out;                 // [B, 1]

    int B = in_sizes[0] / T_STEPS;              // I == 1
    rnn_warp_kernel<<<B, 32>>>(x, W_ih, W_hh, b_ih, b_hh, fc_w, fc_b, out);
}

// round 3
// speedup vs baseline: 1.6787x; 1.0630x over previous
#include <cuda_runtime.h>

#define T_STEPS 512
#define HID 64

typedef unsigned long long ull;

// packed fp32x2 FMA: d.lo += a.lo*b.lo ; d.hi += a.hi*b.hi  (Blackwell FFMA2, PTX-only)
__device__ __forceinline__ void fma2(ull &d, ull a, ull b) {
    asm("fma.rn.f32x2 %0, %1, %2, %0;" : "+l"(d) : "l"(a), "l"(b));
}
__device__ __forceinline__ ull add2(ull a, ull b) {
    ull r;
    asm("add.rn.f32x2 %0, %1, %2;" : "=l"(r) : "l"(a), "l"(b));
    return r;
}
__device__ __forceinline__ float hsum2(ull v) {
    float lo, hi;
    asm("mov.b64 {%0,%1}, %2;" : "=f"(lo), "=f"(hi) : "l"(v));
    return lo + hi;
}

// tanh(x) = 1 - 2/(e^{2x}+1).  __expf -> MUFU.EX2, __fdividef -> MUFU.RCP.
// abs err ~1e-7 << 1e-3 budget.
__device__ __forceinline__ float tanh_fast(float x) {
    float xc = fminf(fmaxf(x, -10.0f), 10.0f);
    float e  = __expf(xc + xc);
    return 1.0f - __fdividef(2.0f, e + 1.0f);
}

// One warp processes TWO batch elements, amortizing the register-resident W_hh
// (rows lane & lane+32, 128 regs) over both. 8 independent FFMA2 chains/step.
// grid = B/2 = 1024 -> single wave at >=11 CTAs/SM residency (no straggler tail).
__global__ void rnn_warp2_kernel(const float* __restrict__ x,
                                 const float* __restrict__ W_ih,
                                 const float* __restrict__ W_hh,
                                 const float* __restrict__ b_ih,
                                 const float* __restrict__ b_hh,
                                 const float* __restrict__ fc_w,
                                 const float* __restrict__ fc_b,
                                 float* __restrict__ out)
{
    __shared__ __align__(16) float sx0[T_STEPS];
    __shared__ __align__(16) float sx1[T_STEPS];
    __shared__ __align__(16) float hbuf[2][2][HID];   // [pingpong][batch][h]

    const int lane = threadIdx.x;        // lane owns output rows (lane, lane+32)
    const int b0   = 2 * blockIdx.x;     // batches b0, b0+1

    // W_hh rows `lane` and `lane+32`, register-resident as f32x2 j-pairs (128 regs).
    ull w0[32], w1[32];
    const ull* wr0 = reinterpret_cast<const ull*>(W_hh + lane * HID);
    const ull* wr1 = reinterpret_cast<const ull*>(W_hh + (lane + 32) * HID);
#pragma unroll
    for (int p = 0; p < 32; ++p) { w0[p] = wr0[p]; w1[p] = wr1[p]; }

    const float wih0  = W_ih[lane];
    const float wih1  = W_ih[lane + 32];
    const float bias0 = b_ih[lane]      + b_hh[lane];
    const float bias1 = b_ih[lane + 32] + b_hh[lane + 32];

    // Stage both batches' x sequences (I=1 => contiguous 512 floats each).
    {
        const float4* xg0 = reinterpret_cast<const float4*>(x + (size_t)b0 * T_STEPS);
        const float4* xg1 = reinterpret_cast<const float4*>(x + (size_t)(b0 + 1) * T_STEPS);
        float4* s0 = reinterpret_cast<float4*>(sx0);
        float4* s1 = reinterpret_cast<float4*>(sx1);
#pragma unroll
        for (int i = 0; i < 4; ++i) {
            s0[lane + 32 * i] = xg0[lane + 32 * i];
            s1[lane + 32 * i] = xg1[lane + 32 * i];
        }
    }

    hbuf[0][0][lane] = 0.0f;  hbuf[0][0][lane + 32] = 0.0f;
    hbuf[0][1][lane] = 0.0f;  hbuf[0][1][lane + 32] = 0.0f;
    __syncwarp();

    auto step = [&](int t, const float (*hr)[HID], float (*hw)[HID]) {
        const ulonglong2* hpA = reinterpret_cast<const ulonglong2*>(hr[0]);
        const ulonglong2* hpB = reinterpret_cast<const ulonglong2*>(hr[1]);
        // 8 independent FFMA2 chains (2 rows x 2 batches x 2 sub-chains... folded to 8 accs)
        ull A0a = 0, A0b = 0, A1a = 0, A1b = 0;   // batch A: rows lane, lane+32
        ull B0a = 0, B0b = 0, B1a = 0, B1b = 0;   // batch B
#pragma unroll
        for (int k = 0; k < 16; ++k) {
            ulonglong2 ha = hpA[k];               // LDS.128 broadcast
            ulonglong2 hb = hpB[k];
            fma2(A0a, ha.x, w0[2 * k]);  fma2(A0b, ha.y, w0[2 * k + 1]);
            fma2(A1a, ha.x, w1[2 * k]);  fma2(A1b, ha.y, w1[2 * k + 1]);
            fma2(B0a, hb.x, w0[2 * k]);  fma2(B0b, hb.y, w0[2 * k + 1]);
            fma2(B1a, hb.x, w1[2 * k]);  fma2(B1b, hb.y, w1[2 * k + 1]);
        }
        float xa = sx0[t], xb = sx1[t];
        float sA0 = hsum2(add2(A0a, A0b)) + fmaf(xa, wih0, bias0);
        float sA1 = hsum2(add2(A1a, A1b)) + fmaf(xa, wih1, bias1);
        float sB0 = hsum2(add2(B0a, B0b)) + fmaf(xb, wih0, bias0);
        float sB1 = hsum2(add2(B1a, B1b)) + fmaf(xb, wih1, bias1);
        hw[0][lane]      = tanh_fast(sA0);
        hw[0][lane + 32] = tanh_fast(sA1);
        hw[1][lane]      = tanh_fast(sB0);
        hw[1][lane + 32] = tanh_fast(sB1);
        __syncwarp();
    };

#pragma unroll 1
    for (int t = 0; t < T_STEPS; t += 2) {
        step(t,     hbuf[0], hbuf[1]);
        step(t + 1, hbuf[1], hbuf[0]);
    }

    // Final FC for both batches: out[b] = sum_h hT[h]*fc_w[h] + fc_b
    const float fw0 = fc_w[lane], fw1 = fc_w[lane + 32];
    float vA = fmaf(hbuf[0][0][lane], fw0, hbuf[0][0][lane + 32] * fw1);
    float vB = fmaf(hbuf[0][1][lane], fw0, hbuf[0][1][lane + 32] * fw1);
#pragma unroll
    for (int o = 16; o; o >>= 1) {
        vA += __shfl_xor_sync(0xffffffffu, vA, o);
        vB += __shfl_xor_sync(0xffffffffu, vB, o);
    }
    if (lane == 0) {
        float fb = fc_b[0];
        out[b0]     = vA + fb;
        out[b0 + 1] = vB + fb;
    }
}

extern "C" void kernel_launch(void* const* d_in, const int* in_sizes, int n_in,
                              void* d_out, int out_size)
{
    const float* x    = (const float*)d_in[0];  // [B, T, 1]
    const float* W_ih = (const float*)d_in[1];  // [64, 1]
    const float* W_hh = (const float*)d_in[2];  // [64, 64]
    const float* b_ih = (const float*)d_in[3];  // [64]
    const float* b_hh = (const float*)d_in[4];  // [64]
    const float* fc_w = (const float*)d_in[5];  // [1, 64]
    const float* fc_b = (const float*)d_in[6];  // [1]
    float* out = (float*)d_out;                 // [B, 1]

    int B = in_sizes[0] / T_STEPS;              // I == 1
    rnn_warp2_kernel<<<B / 2, 32>>>(x, W_ih, W_hh, b_ih, b_hh, fc_w, fc_b, out);
}